// round 2
// baseline (speedup 1.0000x reference)
#include <cuda_runtime.h>
#include <cstdint>
#include <math.h>

#define B_ 256
#define T_ 512
#define I_ 128
#define H_ 256

// Scratch (static device globals — no dynamic allocation allowed).
__device__ float g_xw[(size_t)B_ * T_ * H_];   // [B][T][H] input projection + bias
__device__ float g_h[B_ * H_];                 // final hidden state

// ---------------------------------------------------------------------------
// helpers
// ---------------------------------------------------------------------------
__device__ __forceinline__ void fma2(unsigned long long& acc, unsigned long long a,
                                     unsigned long long b) {
    asm("fma.rn.f32x2 %0, %1, %2, %0;" : "+l"(acc) : "l"(a), "l"(b));
}

__device__ __forceinline__ float unpack_sum(unsigned long long v) {
    float lo, hi;
    asm("mov.b64 {%0,%1}, %2;" : "=f"(lo), "=f"(hi) : "l"(v));
    return lo + hi;
}

__device__ __forceinline__ float red2(unsigned long long a, unsigned long long b) {
    float alo, ahi, blo, bhi;
    asm("mov.b64 {%0,%1}, %2;" : "=f"(alo), "=f"(ahi) : "l"(a));
    asm("mov.b64 {%0,%1}, %2;" : "=f"(blo), "=f"(bhi) : "l"(b));
    return (alo + blo) + (ahi + bhi);
}

__device__ __forceinline__ ulonglong2 pack4(float4 v) {
    ulonglong2 u;
    asm("mov.b64 %0,{%1,%2};" : "=l"(u.x) : "f"(v.x), "f"(v.y));
    asm("mov.b64 %0,{%1,%2};" : "=l"(u.y) : "f"(v.z), "f"(v.w));
    return u;
}

__device__ __forceinline__ uint32_t smem_addr_u32(const void* p) {
    uint32_t a;
    asm("{ .reg .u64 t; cvta.to.shared.u64 t, %1; cvt.u32.u64 %0, t; }"
        : "=r"(a) : "l"(p));
    return a;
}

__device__ __forceinline__ void st_cluster_f32(uint32_t addr, float v) {
    asm volatile("st.shared::cluster.f32 [%0], %1;" :: "r"(addr), "f"(v) : "memory");
}

__device__ __forceinline__ void mbar_wait_parity(uint32_t mb, uint32_t parity) {
    uint32_t done = 0;
    while (!done) {
        asm volatile(
            "{\n\t.reg .pred P;\n\t"
            "mbarrier.try_wait.parity.acquire.cluster.shared::cta.b64 P, [%1], %2, 0x989680;\n\t"
            "selp.b32 %0, 1, 0, P;\n\t}"
            : "=r"(done) : "r"(mb), "r"(parity) : "memory");
    }
}

// ---------------------------------------------------------------------------
// Phase 1: g_xw[b][t][h] = x[b,t,:] . W_ih[h,:] + (b_ih[h]+b_hh[h])
// Block: 256 threads handles 64 (b,t) rows x all 256 H. 2048 blocks.
// W_ih transposed+packed f32x2 in smem [i4][h]; x rows in smem.
// ---------------------------------------------------------------------------
__global__ void __launch_bounds__(256, 1)
xw_kernel(const float* __restrict__ x, const float* __restrict__ Wih,
          const float* __restrict__ bih, const float* __restrict__ bhh) {
    extern __shared__ unsigned char smem_raw[];
    ulonglong2* Ws = (ulonglong2*)smem_raw;               // [32][256]*16B = 128KB
    float*      xs = (float*)(smem_raw + 32 * 256 * 16);  // [64][128] floats = 32KB

    const int tid = threadIdx.x;
    const int b  = blockIdx.x >> 3;
    const int t0 = (blockIdx.x & 7) << 6;

    for (int idx = tid; idx < 32 * 256; idx += 256) {
        int h = idx >> 5, i4 = idx & 31;
        float4 v = ((const float4*)Wih)[h * 32 + i4];
        Ws[i4 * 256 + h] = pack4(v);
    }
    {
        const float4* xg = (const float4*)(x + ((size_t)b * T_ + t0) * I_);
        float4* xs4 = (float4*)xs;
        for (int idx = tid; idx < 64 * 128 / 4; idx += 256) xs4[idx] = xg[idx];
    }
    __syncthreads();

    const int h = tid;
    const float bias = bih[h] + bhh[h];
    const ulonglong2* xs2 = (const ulonglong2*)xs;  // [row][i4]

    for (int half = 0; half < 2; ++half) {
        unsigned long long acc[32];
#pragma unroll
        for (int r = 0; r < 32; ++r) acc[r] = 0ull;

#pragma unroll 2
        for (int k4 = 0; k4 < 32; ++k4) {
            ulonglong2 w = Ws[k4 * 256 + h];
#pragma unroll
            for (int r = 0; r < 32; ++r) {
                ulonglong2 xv = xs2[(half * 32 + r) * 32 + k4];
                fma2(acc[r], w.x, xv.x);
                fma2(acc[r], w.y, xv.y);
            }
        }
#pragma unroll
        for (int r = 0; r < 32; ++r) {
            float s = unpack_sum(acc[r]) + bias;
            g_xw[((size_t)b * T_ + (t0 + half * 32 + r)) * H_ + h] = s;
        }
    }
}

// ---------------------------------------------------------------------------
// Phase 2: recurrent scan. Cluster of 2 CTAs; CTA rank c holds W_hh rows
// [c*128, c*128+128) in smem (f32x2-packed, transposed [k4][jl]). Each
// cluster owns 4 batch rows. Per step each CTA computes its 128 output
// features; halves are exchanged via DSMEM stores + mbarrier handshake.
// Thread = (kh in {0,1}, jl in [0,128)): k-dim split in half, reduced via smem.
// ---------------------------------------------------------------------------
__global__ void __cluster_dims__(2, 1, 1) __launch_bounds__(256, 1)
scan_kernel(const float* __restrict__ Whh) {
    extern __shared__ unsigned char smem_raw[];
    ulonglong2* Ws   = (ulonglong2*)smem_raw;                       // 64*128*16B = 128KB
    float*      hbuf = (float*)(smem_raw + 64 * 128 * 16);          // [2][4][256] = 8KB
    unsigned long long* psum = (unsigned long long*)(hbuf + 2048);  // [128][4] = 4KB
    __shared__ unsigned long long mbar;

    const int tid  = threadIdx.x;
    const int jl   = tid & 127;
    const int kh   = tid >> 7;
    const int rank = blockIdx.x & 1;
    const int b0   = (blockIdx.x >> 1) * 4;
    const int jg   = rank * 128 + jl;

    // load our W_hh half, transpose-pack into [k4][rj]
    for (int idx = tid; idx < 64 * 128; idx += 256) {
        int rj = idx >> 6, k4 = idx & 63;
        float4 v = ((const float4*)Whh)[(rank * 128 + rj) * 64 + k4];
        Ws[k4 * 128 + rj] = pack4(v);
    }
    for (int idx = tid; idx < 2048; idx += 256) hbuf[idx] = 0.0f;  // h0 = 0

    const uint32_t mb_local = smem_addr_u32(&mbar);
    const uint32_t hb_base  = smem_addr_u32(hbuf);
    if (tid == 0) {
        asm volatile("mbarrier.init.shared.b64 [%0], 128;" :: "r"(mb_local) : "memory");
    }
    __syncthreads();
    asm volatile("barrier.cluster.arrive.aligned;" ::: "memory");
    asm volatile("barrier.cluster.wait.aligned;" ::: "memory");

    uint32_t mb_peer, hb_peer;
    {
        uint32_t pr = rank ^ 1;
        asm("mapa.shared::cluster.u32 %0, %1, %2;" : "=r"(mb_peer) : "r"(mb_local), "r"(pr));
        asm("mapa.shared::cluster.u32 %0, %1, %2;" : "=r"(hb_peer) : "r"(hb_base), "r"(pr));
    }

    const float* xwp0 = g_xw + ((size_t)(b0 + 0) * T_) * H_ + jg;
    const float* xwp1 = g_xw + ((size_t)(b0 + 1) * T_) * H_ + jg;
    const float* xwp2 = g_xw + ((size_t)(b0 + 2) * T_) * H_ + jg;
    const float* xwp3 = g_xw + ((size_t)(b0 + 3) * T_) * H_ + jg;

    float cur0 = 0.f, cur1 = 0.f, cur2 = 0.f, cur3 = 0.f;
    if (kh == 0) { cur0 = xwp0[0]; cur1 = xwp1[0]; cur2 = xwp2[0]; cur3 = xwp3[0]; }

    const ulonglong2* wp = Ws + (kh * 32) * 128 + jl;  // stride 128 per k4

    for (int t = 0; t < T_; ++t) {
        const int p = t & 1;
        const ulonglong2* hb2 = (const ulonglong2*)hbuf + p * 256;  // [r*64 + k4]

        unsigned long long a0 = 0, a1 = 0, a2 = 0, a3 = 0;
#pragma unroll
        for (int i = 0; i < 32; ++i) {
            ulonglong2 w  = wp[i * 128];
            int k4 = kh * 32 + i;
            ulonglong2 h0v = hb2[0 * 64 + k4];
            ulonglong2 h1v = hb2[1 * 64 + k4];
            ulonglong2 h2v = hb2[2 * 64 + k4];
            ulonglong2 h3v = hb2[3 * 64 + k4];
            fma2(a0, w.x, h0v.x); fma2(a0, w.y, h0v.y);
            fma2(a1, w.x, h1v.x); fma2(a1, w.y, h1v.y);
            fma2(a2, w.x, h2v.x); fma2(a2, w.y, h2v.y);
            fma2(a3, w.x, h3v.x); fma2(a3, w.y, h3v.y);
        }

        // prefetch next xw (hide DRAM latency behind exchange)
        float n0 = 0.f, n1 = 0.f, n2 = 0.f, n3 = 0.f;
        if (kh == 0 && t + 1 < T_) {
            size_t off = (size_t)(t + 1) * H_;
            n0 = xwp0[off]; n1 = xwp1[off]; n2 = xwp2[off]; n3 = xwp3[off];
        }

        if (kh == 1) {
            psum[jl * 4 + 0] = a0;
            psum[jl * 4 + 1] = a1;
            psum[jl * 4 + 2] = a2;
            psum[jl * 4 + 3] = a3;
        }
        __syncthreads();

        if (kh == 0) {
            float h0 = tanhf(red2(a0, psum[jl * 4 + 0]) + cur0);
            float h1 = tanhf(red2(a1, psum[jl * 4 + 1]) + cur1);
            float h2 = tanhf(red2(a2, psum[jl * 4 + 2]) + cur2);
            float h3 = tanhf(red2(a3, psum[jl * 4 + 3]) + cur3);

            const int p1 = p ^ 1;
            // local stores (our half of next h)
            hbuf[p1 * 1024 + 0 * 256 + jg] = h0;
            hbuf[p1 * 1024 + 1 * 256 + jg] = h1;
            hbuf[p1 * 1024 + 2 * 256 + jg] = h2;
            hbuf[p1 * 1024 + 3 * 256 + jg] = h3;
            // remote stores into peer's hbuf (same offsets)
            uint32_t ra = hb_peer + (uint32_t)(p1 * 1024 + jg) * 4u;
            st_cluster_f32(ra + 0 * 1024, h0);
            st_cluster_f32(ra + 1 * 1024, h1);
            st_cluster_f32(ra + 2 * 1024, h2);
            st_cluster_f32(ra + 3 * 1024, h3);

            if (t == T_ - 1) {
                g_h[(b0 + 0) * H_ + jg] = h0;
                g_h[(b0 + 1) * H_ + jg] = h1;
                g_h[(b0 + 2) * H_ + jg] = h2;
                g_h[(b0 + 3) * H_ + jg] = h3;
            }

            // release-arrive on peer barrier: orders this thread's remote stores
            asm volatile(
                "mbarrier.arrive.release.cluster.shared::cluster.b64 _, [%0];"
                :: "r"(mb_peer) : "memory");

            cur0 = n0; cur1 = n1; cur2 = n2; cur3 = n3;
        }

        // wait for peer's 128 arrivals (peer wrote our other half)
        mbar_wait_parity(mb_local, (uint32_t)(t & 1));
        __syncthreads();
    }
}

// ---------------------------------------------------------------------------
// Phase 3: out[b] = g_h[b,:] . fc_w + fc_b
// ---------------------------------------------------------------------------
__global__ void __launch_bounds__(256)
fc_kernel(const float* __restrict__ fcw, const float* __restrict__ fcb,
          float* __restrict__ out) {
    const int b = blockIdx.x, tid = threadIdx.x;
    float v = g_h[b * H_ + tid] * fcw[tid];
#pragma unroll
    for (int o = 16; o; o >>= 1) v += __shfl_down_sync(0xffffffffu, v, o);
    __shared__ float red[8];
    if ((tid & 31) == 0) red[tid >> 5] = v;
    __syncthreads();
    if (tid == 0) {
        float s = 0.f;
#pragma unroll
        for (int i = 0; i < 8; ++i) s += red[i];
        out[b] = s + fcb[0];
    }
}

// ---------------------------------------------------------------------------
extern "C" void kernel_launch(void* const* d_in, const int* in_sizes, int n_in,
                              void* d_out, int out_size) {
    (void)in_sizes; (void)n_in; (void)out_size;
    const float* x   = (const float*)d_in[0];
    const float* Wih = (const float*)d_in[1];
    const float* Whh = (const float*)d_in[2];
    const float* bih = (const float*)d_in[3];
    const float* bhh = (const float*)d_in[4];
    const float* fcw = (const float*)d_in[5];
    const float* fcb = (const float*)d_in[6];
    float* out = (float*)d_out;

    const int XW_SMEM   = 32 * 256 * 16 + 64 * 128 * 4;      // 163840
    const int SCAN_SMEM = 64 * 128 * 16 + 2048 * 4 + 4096;   // 143360

    cudaFuncSetAttribute(xw_kernel, cudaFuncAttributeMaxDynamicSharedMemorySize, XW_SMEM);
    cudaFuncSetAttribute(scan_kernel, cudaFuncAttributeMaxDynamicSharedMemorySize, SCAN_SMEM);

    xw_kernel<<<2048, 256, XW_SMEM>>>(x, Wih, bih, bhh);
    scan_kernel<<<128, 256, SCAN_SMEM>>>(Whh);
    fc_kernel<<<256, 256>>>(fcw, fcb, out);
}

// round 3
// speedup vs baseline: 1.2077x; 1.2077x over previous
#include <cuda_runtime.h>
#include <cstdint>
#include <math.h>

#define B_ 256
#define T_ 512
#define I_ 128
#define H_ 256

// Scratch (static device globals — no dynamic allocation allowed).
__device__ float g_xw[(size_t)B_ * T_ * H_];   // [B][T][H] input projection + bias
__device__ float g_h[B_ * H_];                 // final hidden state

// ---------------------------------------------------------------------------
// helpers
// ---------------------------------------------------------------------------
__device__ __forceinline__ void fma2(unsigned long long& acc, unsigned long long a,
                                     unsigned long long b) {
    asm("fma.rn.f32x2 %0, %1, %2, %0;" : "+l"(acc) : "l"(a), "l"(b));
}

__device__ __forceinline__ float unpack_sum(unsigned long long v) {
    float lo, hi;
    asm("mov.b64 {%0,%1}, %2;" : "=f"(lo), "=f"(hi) : "l"(v));
    return lo + hi;
}

__device__ __forceinline__ ulonglong2 pack4(float4 v) {
    ulonglong2 u;
    asm("mov.b64 %0,{%1,%2};" : "=l"(u.x) : "f"(v.x), "f"(v.y));
    asm("mov.b64 %0,{%1,%2};" : "=l"(u.y) : "f"(v.z), "f"(v.w));
    return u;
}

__device__ __forceinline__ uint32_t smem_addr_u32(const void* p) {
    uint32_t a;
    asm("{ .reg .u64 t; cvta.to.shared.u64 t, %1; cvt.u32.u64 %0, t; }"
        : "=r"(a) : "l"(p));
    return a;
}

__device__ __forceinline__ void st_cluster_f32(uint32_t addr, float v) {
    asm volatile("st.shared::cluster.f32 [%0], %1;" :: "r"(addr), "f"(v) : "memory");
}

__device__ __forceinline__ void mbar_arrive_cluster(uint32_t addr) {
    asm volatile("mbarrier.arrive.release.cluster.shared::cluster.b64 _, [%0];"
                 :: "r"(addr) : "memory");
}

__device__ __forceinline__ void mbar_wait_parity(uint32_t mb, uint32_t parity) {
    uint32_t done = 0;
    while (!done) {
        asm volatile(
            "{\n\t.reg .pred P;\n\t"
            "mbarrier.try_wait.parity.acquire.cluster.shared::cta.b64 P, [%1], %2, 0x989680;\n\t"
            "selp.b32 %0, 1, 0, P;\n\t}"
            : "=r"(done) : "r"(mb), "r"(parity) : "memory");
    }
}

// ---------------------------------------------------------------------------
// Phase 1: g_xw[b][t][h] = x[b,t,:] . W_ih[h,:] + (b_ih[h]+b_hh[h])
// 256 threads/block, 2 CTAs/SM. Thread h = tid holds its W_ih row in 64 regs.
// Block covers 64 (b,t) rows; x tile (32KB) in smem, read as f32x2 broadcasts.
// ---------------------------------------------------------------------------
__global__ void __launch_bounds__(256, 2)
xw_kernel(const float* __restrict__ x, const float* __restrict__ Wih,
          const float* __restrict__ bih, const float* __restrict__ bhh) {
    __shared__ float xs[64 * 128];  // 32KB

    const int tid = threadIdx.x;
    const int b  = blockIdx.x >> 3;
    const int t0 = (blockIdx.x & 7) << 6;

    // W_ih row for output h=tid -> 32 ulonglong2 regs
    ulonglong2 w[32];
#pragma unroll
    for (int i = 0; i < 32; ++i)
        w[i] = pack4(__ldg(((const float4*)Wih) + tid * 32 + i));

    // x tile: 64 rows x 128
    {
        const float4* xg = (const float4*)(x + ((size_t)b * T_ + t0) * I_);
        float4* xs4 = (float4*)xs;
        for (int idx = tid; idx < 64 * 128 / 4; idx += 256) xs4[idx] = xg[idx];
    }
    const float bias = __ldg(bih + tid) + __ldg(bhh + tid);
    __syncthreads();

    const ulonglong2* xs2 = (const ulonglong2*)xs;  // [row][i4], i4 in [0,32)

    for (int tile = 0; tile < 4; ++tile) {
        unsigned long long acc[16];
#pragma unroll
        for (int r = 0; r < 16; ++r) acc[r] = 0ull;

#pragma unroll 8
        for (int k4 = 0; k4 < 32; ++k4) {
#pragma unroll
            for (int r = 0; r < 16; ++r) {
                ulonglong2 xv = xs2[(tile * 16 + r) * 32 + k4];
                fma2(acc[r], w[k4].x, xv.x);
                fma2(acc[r], w[k4].y, xv.y);
            }
        }
#pragma unroll
        for (int r = 0; r < 16; ++r) {
            float s = unpack_sum(acc[r]) + bias;
            g_xw[((size_t)b * T_ + (t0 + tile * 16 + r)) * H_ + tid] = s;
        }
    }
}

// ---------------------------------------------------------------------------
// Phase 2: recurrent scan. Cluster of 2 CTAs, 512 threads each, 4 batch rows
// per cluster. Thread (kk = tid>>7, jl = tid&127) owns output column
// jg = rank*128+jl and a 64-wide K slice split into an own-CTA half (k in
// rank's j-range, produced locally) and a peer half (arrives via DSMEM).
// W_hh slice lives entirely in registers (16 ulonglong2). Own-half FMA runs
// before the peer mbarrier wait, hiding the DSMEM exchange latency.
// Epilogue: thread finalizes exactly one element (row kk, column jg).
// ---------------------------------------------------------------------------
__global__ void __cluster_dims__(2, 1, 1) __launch_bounds__(512, 1)
scan_kernel(const float* __restrict__ Whh) {
    __shared__ float hbuf[2][4][256];                 // [parity][row][k] = 8KB
    __shared__ unsigned long long psum[4][4][128];    // [kk][row][jl]    = 16KB
    __shared__ unsigned long long mbar;               // peer-arrival barrier

    const int tid  = threadIdx.x;
    const int jl   = tid & 127;
    const int kk   = tid >> 7;           // 0..3
    const int rank = blockIdx.x & 1;
    const int b0   = (blockIdx.x >> 1) * 4;
    const int jg   = rank * 128 + jl;

    // W_hh[jg][k] slices -> regs. own: k4 in [rank*32 + kk*8, +8)
    //                        peer: k4 in [(1-rank)*32 + kk*8, +8)
    const int k4o = rank * 32 + kk * 8;
    const int k4p = (1 - rank) * 32 + kk * 8;
    ulonglong2 wo[8], wp[8];
#pragma unroll
    for (int i = 0; i < 8; ++i) {
        wo[i] = pack4(__ldg(((const float4*)Whh) + jg * 64 + k4o + i));
        wp[i] = pack4(__ldg(((const float4*)Whh) + jg * 64 + k4p + i));
    }

    // zero both h parity buffers
    for (int idx = tid; idx < 2 * 4 * 256; idx += 512)
        ((float*)hbuf)[idx] = 0.0f;

    const uint32_t mb_local = smem_addr_u32(&mbar);
    const uint32_t hb_base  = smem_addr_u32(&hbuf[0][0][0]);
    if (tid == 0) {
        asm volatile("mbarrier.init.shared.b64 [%0], 512;" :: "r"(mb_local) : "memory");
    }
    __syncthreads();
    asm volatile("barrier.cluster.arrive.aligned;" ::: "memory");
    asm volatile("barrier.cluster.wait.aligned;" ::: "memory");

    uint32_t mb_peer, hb_peer;
    {
        uint32_t pr = rank ^ 1;
        asm("mapa.shared::cluster.u32 %0, %1, %2;" : "=r"(mb_peer) : "r"(mb_local), "r"(pr));
        asm("mapa.shared::cluster.u32 %0, %1, %2;" : "=r"(hb_peer) : "r"(hb_base), "r"(pr));
    }

    // complete phase 0 of the peer barrier so the t=0 wait passes immediately
    mbar_arrive_cluster(mb_peer);

    // xw stream: thread covers (row kk, column jg)
    const float* xwp = g_xw + ((size_t)(b0 + kk) * T_) * H_ + jg;
    float cur = __ldg(xwp);

    for (int t = 0; t < T_; ++t) {
        const int p = t & 1;
        const ulonglong2* hb2 = (const ulonglong2*)hbuf[p];  // [row*64 + k4]

        unsigned long long a0 = 0, a1 = 0, a2 = 0, a3 = 0;

        // own-CTA half (local hbuf data, ordered by last step's __syncthreads)
#pragma unroll
        for (int i = 0; i < 8; ++i) {
            ulonglong2 w = wo[i];
            int k4 = k4o + i;
            ulonglong2 h0v = hb2[0 * 64 + k4];
            ulonglong2 h1v = hb2[1 * 64 + k4];
            ulonglong2 h2v = hb2[2 * 64 + k4];
            ulonglong2 h3v = hb2[3 * 64 + k4];
            fma2(a0, w.x, h0v.x); fma2(a0, w.y, h0v.y);
            fma2(a1, w.x, h1v.x); fma2(a1, w.y, h1v.y);
            fma2(a2, w.x, h2v.x); fma2(a2, w.y, h2v.y);
            fma2(a3, w.x, h3v.x); fma2(a3, w.y, h3v.y);
        }

        // prefetch next xw while waiting for peer half
        float nxt = 0.0f;
        if (t + 1 < T_) nxt = __ldg(xwp + (size_t)(t + 1) * H_);

        // wait for peer's h half (arrivals from peer's step t-1 epilogue)
        mbar_wait_parity(mb_local, (uint32_t)(t & 1));

        // peer half
#pragma unroll
        for (int i = 0; i < 8; ++i) {
            ulonglong2 w = wp[i];
            int k4 = k4p + i;
            ulonglong2 h0v = hb2[0 * 64 + k4];
            ulonglong2 h1v = hb2[1 * 64 + k4];
            ulonglong2 h2v = hb2[2 * 64 + k4];
            ulonglong2 h3v = hb2[3 * 64 + k4];
            fma2(a0, w.x, h0v.x); fma2(a0, w.y, h0v.y);
            fma2(a1, w.x, h1v.x); fma2(a1, w.y, h1v.y);
            fma2(a2, w.x, h2v.x); fma2(a2, w.y, h2v.y);
            fma2(a3, w.x, h3v.x); fma2(a3, w.y, h3v.y);
        }

        // share partials for the rows this thread does NOT finalize
        if (kk != 0) psum[kk][0][jl] = a0;
        if (kk != 1) psum[kk][1][jl] = a1;
        if (kk != 2) psum[kk][2][jl] = a2;
        if (kk != 3) psum[kk][3][jl] = a3;
        __syncthreads();

        // finalize (row kk, column jg)
        unsigned long long mine = (kk == 0) ? a0 : (kk == 1) ? a1 : (kk == 2) ? a2 : a3;
        float s = unpack_sum(mine);
#pragma unroll
        for (int q = 0; q < 4; ++q)
            if (q != kk) s += unpack_sum(psum[q][kk][jl]);

        float h = tanhf(s + cur);
        cur = nxt;

        const int p1 = p ^ 1;
        hbuf[p1][kk][jg] = h;
        if (t + 1 < T_) {
            st_cluster_f32(hb_peer + (uint32_t)(p1 * 1024 + kk * 256 + jg) * 4u, h);
            mbar_arrive_cluster(mb_peer);
        } else {
            g_h[(b0 + kk) * H_ + jg] = h;
        }
        __syncthreads();  // local hbuf[p1] visible to all own threads
    }
}

// ---------------------------------------------------------------------------
// Phase 3: out[b] = g_h[b,:] . fc_w + fc_b
// ---------------------------------------------------------------------------
__global__ void __launch_bounds__(256)
fc_kernel(const float* __restrict__ fcw, const float* __restrict__ fcb,
          float* __restrict__ out) {
    const int b = blockIdx.x, tid = threadIdx.x;
    float v = g_h[b * H_ + tid] * __ldg(fcw + tid);
#pragma unroll
    for (int o = 16; o; o >>= 1) v += __shfl_down_sync(0xffffffffu, v, o);
    __shared__ float red[8];
    if ((tid & 31) == 0) red[tid >> 5] = v;
    __syncthreads();
    if (tid == 0) {
        float s = 0.f;
#pragma unroll
        for (int i = 0; i < 8; ++i) s += red[i];
        out[b] = s + __ldg(fcb);
    }
}

// ---------------------------------------------------------------------------
extern "C" void kernel_launch(void* const* d_in, const int* in_sizes, int n_in,
                              void* d_out, int out_size) {
    (void)in_sizes; (void)n_in; (void)out_size;
    const float* x   = (const float*)d_in[0];
    const float* Wih = (const float*)d_in[1];
    const float* Whh = (const float*)d_in[2];
    const float* bih = (const float*)d_in[3];
    const float* bhh = (const float*)d_in[4];
    const float* fcw = (const float*)d_in[5];
    const float* fcb = (const float*)d_in[6];
    float* out = (float*)d_out;

    xw_kernel<<<2048, 256>>>(x, Wih, bih, bhh);
    scan_kernel<<<128, 512>>>(Whh);
    fc_kernel<<<256, 256>>>(fcw, fcb, out);
}

// round 4
// speedup vs baseline: 1.3312x; 1.1022x over previous
#include <cuda_runtime.h>
#include <cstdint>
#include <math.h>

#define B_ 256
#define T_ 512
#define I_ 128
#define H_ 256

typedef unsigned long long ull;

// Scratch (static device globals — no dynamic allocation allowed).
__device__ float g_xw[(size_t)B_ * T_ * H_];   // [B][T][H] input projection + bias
__device__ float g_h[B_ * H_];                 // final hidden state

// ---------------------------------------------------------------------------
// helpers
// ---------------------------------------------------------------------------
__device__ __forceinline__ void fma2(ull& acc, ull a, ull b) {
    asm("fma.rn.f32x2 %0, %1, %2, %0;" : "+l"(acc) : "l"(a), "l"(b));
}

__device__ __forceinline__ float unpack_sum(ull v) {
    float lo, hi;
    asm("mov.b64 {%0,%1}, %2;" : "=f"(lo), "=f"(hi) : "l"(v));
    return lo + hi;
}

__device__ __forceinline__ float red2(ull a, ull b) {
    float alo, ahi, blo, bhi;
    asm("mov.b64 {%0,%1}, %2;" : "=f"(alo), "=f"(ahi) : "l"(a));
    asm("mov.b64 {%0,%1}, %2;" : "=f"(blo), "=f"(bhi) : "l"(b));
    return (alo + blo) + (ahi + bhi);
}

__device__ __forceinline__ ulonglong2 pack4(float4 v) {
    ulonglong2 u;
    asm("mov.b64 %0,{%1,%2};" : "=l"(u.x) : "f"(v.x), "f"(v.y));
    asm("mov.b64 %0,{%1,%2};" : "=l"(u.y) : "f"(v.z), "f"(v.w));
    return u;
}

// ---------------------------------------------------------------------------
// Phase 1: g_xw[b][t][h] = x[b,t,:] . W_ih[h,:] + (b_ih[h]+b_hh[h])
// (unchanged from R2 — isolating the scan change this round)
// ---------------------------------------------------------------------------
__global__ void __launch_bounds__(256, 2)
xw_kernel(const float* __restrict__ x, const float* __restrict__ Wih,
          const float* __restrict__ bih, const float* __restrict__ bhh) {
    __shared__ float xs[64 * 128];  // 32KB

    const int tid = threadIdx.x;
    const int b  = blockIdx.x >> 3;
    const int t0 = (blockIdx.x & 7) << 6;

    ulonglong2 w[32];
#pragma unroll
    for (int i = 0; i < 32; ++i)
        w[i] = pack4(__ldg(((const float4*)Wih) + tid * 32 + i));

    {
        const float4* xg = (const float4*)(x + ((size_t)b * T_ + t0) * I_);
        float4* xs4 = (float4*)xs;
        for (int idx = tid; idx < 64 * 128 / 4; idx += 256) xs4[idx] = xg[idx];
    }
    const float bias = __ldg(bih + tid) + __ldg(bhh + tid);
    __syncthreads();

    const ulonglong2* xs2 = (const ulonglong2*)xs;

    for (int tile = 0; tile < 4; ++tile) {
        ull acc[16];
#pragma unroll
        for (int r = 0; r < 16; ++r) acc[r] = 0ull;

#pragma unroll 8
        for (int k4 = 0; k4 < 32; ++k4) {
#pragma unroll
            for (int r = 0; r < 16; ++r) {
                ulonglong2 xv = xs2[(tile * 16 + r) * 32 + k4];
                fma2(acc[r], w[k4].x, xv.x);
                fma2(acc[r], w[k4].y, xv.y);
            }
        }
#pragma unroll
        for (int r = 0; r < 16; ++r) {
            float s = unpack_sum(acc[r]) + bias;
            g_xw[((size_t)b * T_ + (t0 + tile * 16 + r)) * H_ + tid] = s;
        }
    }
}

// ---------------------------------------------------------------------------
// Phase 2: recurrent scan — single-CTA, no cluster.
// 128 CTAs x 512 threads; CTA owns batch rows b0, b0+1 for all 512 steps.
// Thread (j = tid&255, kh = tid>>8) owns output column j with K-half kh.
// W_hh[j][kh-half] = 128 floats: first 80 in registers (40 ull), last 48 in
// smem (12 ulonglong2 per thread, per-lane conflict-free LDS.128).
// h (2 rows x 256 fp32, 2KB) in smem, read as uniform broadcasts.
// Reduction: thread writes its partial for row (1-kh) to psum, reads the
// partner's partial for row kh, finalizes h[row=kh][j]. 2 syncthreads/step.
// ---------------------------------------------------------------------------
#define NRK 40   // k2-pairs of W in registers per thread (80 floats)
#define NSK 12   // ulonglong2 (2 k2 each) of W in smem per thread (48 floats)

__global__ void __launch_bounds__(512, 1)
scan_kernel(const float* __restrict__ Whh) {
    extern __shared__ unsigned char smem_raw[];
    ulonglong2* Wsm2 = (ulonglong2*)smem_raw;                    // [2*NSK][256] = 96KB
    float*      hbuf = (float*)(smem_raw + 2 * NSK * 256 * 16);  // [2][256]    = 2KB
    ull*        psum = (ull*)(hbuf + 512);                       // [2][256]    = 4KB

    const int tid = threadIdx.x;
    const int j   = tid & 255;
    const int kh  = tid >> 8;            // 0 or 1
    const int b0  = blockIdx.x * 2;

    // --- W_hh slice: k2 in [kh*64, kh*64+64). First NRK in regs, rest in smem.
    const ull* Wrow = (const ull*)(Whh + (size_t)j * H_);  // 128 ull (k2 pairs)
    ull wr[NRK];
#pragma unroll
    for (int i = 0; i < NRK; ++i)
        wr[i] = __ldg(Wrow + kh * 64 + i);

    {
        const ulonglong2* Wrow2 = (const ulonglong2*)Wrow;  // 16B-aligned (k2 even)
#pragma unroll
        for (int p = 0; p < NSK; ++p) {
            // covers k2 = kh*64 + NRK + 2p, +1  ->  ull2 index (kh*64+NRK)/2 + p
            Wsm2[(kh * NSK + p) * 256 + j] = __ldg(Wrow2 + (kh * 64 + NRK) / 2 + p);
        }
    }

    // h0 = 0
    if (tid < 512) hbuf[tid] = 0.0f;
    __syncthreads();

    // xw stream for (row kh, column j)
    const float* xwp = g_xw + ((size_t)(b0 + kh) * T_) * H_ + j;
    float cur = __ldg(xwp);

    const ulonglong2* h0p = (const ulonglong2*)(hbuf)       + kh * 32;  // row 0, my k-half
    const ulonglong2* h1p = (const ulonglong2*)(hbuf + 256) + kh * 32;  // row 1
    const ulonglong2* wsp = Wsm2 + (kh * NSK) * 256 + j;                // stride 256/p

    for (int t = 0; t < T_; ++t) {
        // prefetch next xw early (gmem latency hidden behind FMA phase)
        float nxt = 0.0f;
        if (t + 1 < T_) nxt = __ldg(xwp + (size_t)(t + 1) * H_);

        ull a0 = 0, a1 = 0;

        // register-W part: 20 ull2 h-loads per row, 80 FFMA2
#pragma unroll
        for (int i2 = 0; i2 < NRK / 2; ++i2) {
            ulonglong2 h0 = h0p[i2];
            ulonglong2 h1 = h1p[i2];
            fma2(a0, wr[2 * i2], h0.x);     fma2(a0, wr[2 * i2 + 1], h0.y);
            fma2(a1, wr[2 * i2], h1.x);     fma2(a1, wr[2 * i2 + 1], h1.y);
        }
        // smem-W part: 12 per-lane W loads + 24 h-loads, 48 FFMA2
#pragma unroll
        for (int p = 0; p < NSK; ++p) {
            ulonglong2 w  = wsp[p * 256];
            ulonglong2 h0 = h0p[NRK / 2 + p];
            ulonglong2 h1 = h1p[NRK / 2 + p];
            fma2(a0, w.x, h0.x);  fma2(a0, w.y, h0.y);
            fma2(a1, w.x, h1.x);  fma2(a1, w.y, h1.y);
        }

        // share partial for the row I don't finalize
        psum[(1 - kh) * 256 + j] = kh ? a0 : a1;
        __syncthreads();

        // finalize (row kh, column j): my acc + partner's partial
        ull mine  = kh ? a1 : a0;
        float s   = red2(mine, psum[kh * 256 + j]) + cur;
        float h   = tanhf(s);
        cur = nxt;

        hbuf[kh * 256 + j] = h;
        if (t == T_ - 1) g_h[(b0 + kh) * H_ + j] = h;
        __syncthreads();
    }
}

// ---------------------------------------------------------------------------
// Phase 3: out[b] = g_h[b,:] . fc_w + fc_b
// ---------------------------------------------------------------------------
__global__ void __launch_bounds__(256)
fc_kernel(const float* __restrict__ fcw, const float* __restrict__ fcb,
          float* __restrict__ out) {
    const int b = blockIdx.x, tid = threadIdx.x;
    float v = g_h[b * H_ + tid] * __ldg(fcw + tid);
#pragma unroll
    for (int o = 16; o; o >>= 1) v += __shfl_down_sync(0xffffffffu, v, o);
    __shared__ float red[8];
    if ((tid & 31) == 0) red[tid >> 5] = v;
    __syncthreads();
    if (tid == 0) {
        float s = 0.f;
#pragma unroll
        for (int i = 0; i < 8; ++i) s += red[i];
        out[b] = s + __ldg(fcb);
    }
}

// ---------------------------------------------------------------------------
extern "C" void kernel_launch(void* const* d_in, const int* in_sizes, int n_in,
                              void* d_out, int out_size) {
    (void)in_sizes; (void)n_in; (void)out_size;
    const float* x   = (const float*)d_in[0];
    const float* Wih = (const float*)d_in[1];
    const float* Whh = (const float*)d_in[2];
    const float* bih = (const float*)d_in[3];
    const float* bhh = (const float*)d_in[4];
    const float* fcw = (const float*)d_in[5];
    const float* fcb = (const float*)d_in[6];
    float* out = (float*)d_out;

    const int SCAN_SMEM = 2 * NSK * 256 * 16 + 512 * 4 + 512 * 8;  // 96KB + 2KB + 4KB

    cudaFuncSetAttribute(scan_kernel, cudaFuncAttributeMaxDynamicSharedMemorySize, SCAN_SMEM);

    xw_kernel<<<2048, 256>>>(x, Wih, bih, bhh);
    scan_kernel<<<128, 512, SCAN_SMEM>>>(Whh);
    fc_kernel<<<256, 256>>>(fcw, fcb, out);
}

// round 5
// speedup vs baseline: 1.4645x; 1.1002x over previous
#include <cuda_runtime.h>
#include <cstdint>
#include <math.h>

#define B_ 256
#define T_ 512
#define I_ 128
#define H_ 256

typedef unsigned long long ull;

// Scratch (static device globals — no dynamic allocation allowed).
__device__ float g_xw[(size_t)B_ * T_ * H_];   // [B][T][H] input projection + bias
__device__ float g_h[B_ * H_];                 // final hidden state
__device__ ull   g_wpack[I_ * (H_ / 2)];       // W_ih packed: [k][j2] ull = {W[2j2][k], W[2j2+1][k]}

// ---------------------------------------------------------------------------
// helpers
// ---------------------------------------------------------------------------
__device__ __forceinline__ void fma2(ull& acc, ull a, ull b) {
    asm("fma.rn.f32x2 %0, %1, %2, %0;" : "+l"(acc) : "l"(a), "l"(b));
}

__device__ __forceinline__ float unpack_sum(ull v) {
    float lo, hi;
    asm("mov.b64 {%0,%1}, %2;" : "=f"(lo), "=f"(hi) : "l"(v));
    return lo + hi;
}

__device__ __forceinline__ float2 unpack2(ull v) {
    float2 r;
    asm("mov.b64 {%0,%1}, %2;" : "=f"(r.x), "=f"(r.y) : "l"(v));
    return r;
}

__device__ __forceinline__ ull pack2(float a, float b) {
    ull u;
    asm("mov.b64 %0,{%1,%2};" : "=l"(u) : "f"(a), "f"(b));
    return u;
}

__device__ __forceinline__ ull dup1(float a) {
    ull u;
    asm("mov.b64 %0,{%1,%1};" : "=l"(u) : "f"(a));
    return u;
}

// ---------------------------------------------------------------------------
// Phase 0: pack W_ih k-major with j-pairs: g_wpack[k][j2] = {W[2j2][k], W[2j2+1][k]}
// ---------------------------------------------------------------------------
__global__ void __launch_bounds__(256)
wpack_kernel(const float* __restrict__ Wih) {
    int t = blockIdx.x * 256 + threadIdx.x;   // 16384 total
    int j2 = t & 127, k = t >> 7;
    float a = __ldg(Wih + (2 * j2) * I_ + k);
    float b = __ldg(Wih + (2 * j2 + 1) * I_ + k);
    g_wpack[k * 128 + j2] = pack2(a, b);
}

// ---------------------------------------------------------------------------
// Phase 1: g_xw[row][j] = x[row,:] . W_ih[j,:] + bias[j],  row = b*T + t.
// Register-tiled f32x2 GEMM: 128 rows x 128 j per block, 256 threads,
// 8 rows x 8 j per thread (j's = 2*(tx+16*jj)+{0,1}).
// smem: x duplicated as {v,v} ull [128 r][128 k] = 128KB; W packed [128 k][64 j2] = 64KB.
// Per k: 8 LDS.64 x (2-addr broadcast) + 4 LDS.64 W (per-lane) + 32 FFMA2.
// ---------------------------------------------------------------------------
__global__ void __launch_bounds__(256, 1)
xw_kernel(const float* __restrict__ x,
          const float* __restrict__ bih, const float* __restrict__ bhh) {
    extern __shared__ unsigned char smem_raw[];
    ull* xs = (ull*)smem_raw;                       // [r][k] dup, 128KB
    ull* ws = (ull*)(smem_raw + 128 * 128 * 8);     // [k][j2l], 64KB

    const int tid = threadIdx.x;
    const int jt  = blockIdx.x & 1;          // j-half
    const int rt  = blockIdx.x >> 1;         // row tile
    const int tx  = tid & 15;
    const int ty  = tid >> 4;

    // load x tile (coalesced), store duplicated
    {
        const float4* xg = (const float4*)(x + (size_t)rt * 128 * I_);
        for (int i = 0; i < 16; ++i) {
            int lin = tid + i * 256;                   // 4096 float4
            float4 v = __ldg(xg + lin);
            int r = lin >> 5, kc = lin & 31;
            ulonglong2* d = (ulonglong2*)(xs + r * 128 + kc * 4);
            ulonglong2 u0; u0.x = dup1(v.x); u0.y = dup1(v.y);
            ulonglong2 u1; u1.x = dup1(v.z); u1.y = dup1(v.w);
            d[0] = u0; d[1] = u1;
        }
    }
    // load W tile (coalesced from pre-packed)
    {
        const ulonglong2* wg = (const ulonglong2*)g_wpack;
        ulonglong2* wd = (ulonglong2*)ws;
        for (int i = 0; i < 16; ++i) {
            int lin = tid + i * 256;                   // 4096 ull2
            int k = lin >> 5, c = lin & 31;
            wd[k * 32 + c] = __ldg(wg + k * 64 + jt * 32 + c);
        }
    }
    __syncthreads();

    ull acc[8][4];
#pragma unroll
    for (int r = 0; r < 8; ++r)
#pragma unroll
        for (int j = 0; j < 4; ++j) acc[r][j] = 0ull;

    const ull* xrow = xs + (ty * 8) * 128;   // 8 rows, stride 128
    const ull* wcol = ws + tx;               // + jj*16, stride 64 per k

#pragma unroll 4
    for (int k = 0; k < 128; ++k) {
        ull wv[4];
#pragma unroll
        for (int jj = 0; jj < 4; ++jj) wv[jj] = wcol[k * 64 + jj * 16];
#pragma unroll
        for (int r = 0; r < 8; ++r) {
            ull xv = xrow[r * 128 + k];
#pragma unroll
            for (int jj = 0; jj < 4; ++jj) fma2(acc[r][jj], xv, wv[jj]);
        }
    }

    // bias + store
    float2 bb[4];
#pragma unroll
    for (int jj = 0; jj < 4; ++jj) {
        int j2 = jt * 64 + tx + 16 * jj;
        float2 b1 = __ldg(((const float2*)bih) + j2);
        float2 b2 = __ldg(((const float2*)bhh) + j2);
        bb[jj].x = b1.x + b2.x; bb[jj].y = b1.y + b2.y;
    }
    float2* outg = (float2*)g_xw;
#pragma unroll
    for (int r = 0; r < 8; ++r) {
        size_t row = (size_t)rt * 128 + ty * 8 + r;
#pragma unroll
        for (int jj = 0; jj < 4; ++jj) {
            float2 v = unpack2(acc[r][jj]);
            v.x += bb[jj].x; v.y += bb[jj].y;
            outg[row * 128 + jt * 64 + tx + 16 * jj] = v;
        }
    }
}

// ---------------------------------------------------------------------------
// Phase 2: recurrent scan — single CTA per 2 batch rows, 128 CTAs x 512 thr.
// Thread (jp = tid&127, kq = tid>>7) owns j0=2jp, j1=2jp+1 with k-slice
// [kq*64, kq*64+64). W: 22 k2-ulls per j in regs (88 regs), 5 ull2 per j in
// smem (per-lane LDS.128). h broadcasts feed 8 FFMA2 each (2 j x 2 rows).
// 4-way k-reduction via ulonglong2 psum; finalizers (kq<2) do row=kq.
// ---------------------------------------------------------------------------
#define NRKJ 22   // k2 (ull) per j in registers
#define NSKJ 5    // ull2 per j in smem  (22 + 10 k2 = 32 k2 = 64 k)

__global__ void __launch_bounds__(512, 1)
scan_kernel(const float* __restrict__ Whh) {
    extern __shared__ unsigned char smem_raw[];
    ulonglong2* Wsm = (ulonglong2*)smem_raw;                    // [4][NSKJ][2][128] = 80KB
    float* hbuf = (float*)(smem_raw + 4 * NSKJ * 2 * 128 * 16); // [2][2][256] = 4KB
    ulonglong2* psum = (ulonglong2*)(hbuf + 1024);              // [2][3][128] = 12KB

    const int tid = threadIdx.x;
    const int jp  = tid & 127;
    const int kq  = tid >> 7;            // 0..3
    const int j0  = 2 * jp;
    const int b0  = blockIdx.x * 2;

    // W register slices (k2 idx kq*32 .. kq*32+21)
    const ull* Wr0 = (const ull*)(Whh + (size_t)j0 * H_) + kq * 32;
    const ull* Wr1 = (const ull*)(Whh + (size_t)(j0 + 1) * H_) + kq * 32;
    ull w0[NRKJ], w1[NRKJ];
#pragma unroll
    for (int i = 0; i < NRKJ; ++i) { w0[i] = __ldg(Wr0 + i); w1[i] = __ldg(Wr1 + i); }

    // W smem slices (h-ull2 idx 11..15 of my k-slice)
    {
        const ulonglong2* W20 = (const ulonglong2*)(Whh + (size_t)j0 * H_);
        const ulonglong2* W21 = (const ulonglong2*)(Whh + (size_t)(j0 + 1) * H_);
#pragma unroll
        for (int p = 0; p < NSKJ; ++p) {
            Wsm[((kq * NSKJ + p) * 2 + 0) * 128 + jp] = __ldg(W20 + kq * 16 + 11 + p);
            Wsm[((kq * NSKJ + p) * 2 + 1) * 128 + jp] = __ldg(W21 + kq * 16 + 11 + p);
        }
    }

    // h0 = 0 (both parities)
    hbuf[tid] = 0.0f; hbuf[512 + tid] = 0.0f;
    __syncthreads();

    const ulonglong2* hb  = (const ulonglong2*)hbuf;            // [p*128 + row*64 + k4]
    const ulonglong2* wsp = Wsm + (kq * NSKJ * 2) * 128 + jp;

    // xw stream: finalizers (kq<2) track row (b0+kq), cols (j0, j0+1)
    const float2* xwp = ((const float2*)g_xw) + ((size_t)(b0 + kq) * T_) * 128 + jp;
    float2 cur = make_float2(0.f, 0.f);
    if (kq < 2) cur = __ldg(xwp);

    for (int t = 0; t < T_; ++t) {
        const int p = t & 1;
        const ulonglong2* h0p = hb + p * 128 + kq * 16;        // row 0
        const ulonglong2* h1p = hb + p * 128 + 64 + kq * 16;   // row 1

        ull a00 = 0, a01 = 0, a10 = 0, a11 = 0;  // a[j][row]

#pragma unroll
        for (int i2 = 0; i2 < 11; ++i2) {
            ulonglong2 h0 = h0p[i2], h1 = h1p[i2];
            fma2(a00, w0[2 * i2], h0.x); fma2(a00, w0[2 * i2 + 1], h0.y);
            fma2(a01, w0[2 * i2], h1.x); fma2(a01, w0[2 * i2 + 1], h1.y);
            fma2(a10, w1[2 * i2], h0.x); fma2(a10, w1[2 * i2 + 1], h0.y);
            fma2(a11, w1[2 * i2], h1.x); fma2(a11, w1[2 * i2 + 1], h1.y);
        }
#pragma unroll
        for (int pp = 0; pp < NSKJ; ++pp) {
            ulonglong2 wa = wsp[(pp * 2 + 0) * 128];
            ulonglong2 wb = wsp[(pp * 2 + 1) * 128];
            ulonglong2 h0 = h0p[11 + pp], h1 = h1p[11 + pp];
            fma2(a00, wa.x, h0.x); fma2(a00, wa.y, h0.y);
            fma2(a01, wa.x, h1.x); fma2(a01, wa.y, h1.y);
            fma2(a10, wb.x, h0.x); fma2(a10, wb.y, h0.y);
            fma2(a11, wb.x, h1.x); fma2(a11, wb.y, h1.y);
        }

        // prefetch next xw
        float2 nxt = make_float2(0.f, 0.f);
        if (kq < 2 && t + 1 < T_) nxt = __ldg(xwp + (size_t)(t + 1) * 128);

        // share partials: psum[row][slot][jp] = {j0 partial, j1 partial}
        {
            ulonglong2 v;
            if (kq == 0) { v.x = a01; v.y = a11; psum[1 * 384 + 0 * 128 + jp] = v; }
            else if (kq == 1) { v.x = a00; v.y = a10; psum[0 * 384 + 0 * 128 + jp] = v; }
            else {
                int s = kq - 1;  // 1 or 2
                v.x = a00; v.y = a10; psum[0 * 384 + s * 128 + jp] = v;
                ulonglong2 u; u.x = a01; u.y = a11; psum[1 * 384 + s * 128 + jp] = u;
            }
        }
        __syncthreads();

        if (kq < 2) {
            float s0 = unpack_sum(kq == 0 ? a00 : a01) + cur.x;
            float s1 = unpack_sum(kq == 0 ? a10 : a11) + cur.y;
#pragma unroll
            for (int s = 0; s < 3; ++s) {
                ulonglong2 ps = psum[kq * 384 + s * 128 + jp];
                s0 += unpack_sum(ps.x);
                s1 += unpack_sum(ps.y);
            }
            float hv0 = tanhf(s0), hv1 = tanhf(s1);
            ((float2*)hbuf)[((p ^ 1) * 2 + kq) * 128 + jp] = make_float2(hv0, hv1);
            if (t == T_ - 1)
                ((float2*)g_h)[(b0 + kq) * 128 + jp] = make_float2(hv0, hv1);
            cur = nxt;
        }
        __syncthreads();
    }
}

// ---------------------------------------------------------------------------
// Phase 3: out[b] = g_h[b,:] . fc_w + fc_b
// ---------------------------------------------------------------------------
__global__ void __launch_bounds__(256)
fc_kernel(const float* __restrict__ fcw, const float* __restrict__ fcb,
          float* __restrict__ out) {
    const int b = blockIdx.x, tid = threadIdx.x;
    float v = g_h[b * H_ + tid] * __ldg(fcw + tid);
#pragma unroll
    for (int o = 16; o; o >>= 1) v += __shfl_down_sync(0xffffffffu, v, o);
    __shared__ float red[8];
    if ((tid & 31) == 0) red[tid >> 5] = v;
    __syncthreads();
    if (tid == 0) {
        float s = 0.f;
#pragma unroll
        for (int i = 0; i < 8; ++i) s += red[i];
        out[b] = s + __ldg(fcb);
    }
}

// ---------------------------------------------------------------------------
extern "C" void kernel_launch(void* const* d_in, const int* in_sizes, int n_in,
                              void* d_out, int out_size) {
    (void)in_sizes; (void)n_in; (void)out_size;
    const float* x   = (const float*)d_in[0];
    const float* Wih = (const float*)d_in[1];
    const float* Whh = (const float*)d_in[2];
    const float* bih = (const float*)d_in[3];
    const float* bhh = (const float*)d_in[4];
    const float* fcw = (const float*)d_in[5];
    const float* fcb = (const float*)d_in[6];
    float* out = (float*)d_out;

    const int XW_SMEM   = 128 * 128 * 8 + 128 * 64 * 8;            // 192KB
    const int SCAN_SMEM = 4 * NSKJ * 2 * 128 * 16 + 1024 * 4 + 2 * 3 * 128 * 16;  // 96KB

    cudaFuncSetAttribute(xw_kernel, cudaFuncAttributeMaxDynamicSharedMemorySize, XW_SMEM);
    cudaFuncSetAttribute(scan_kernel, cudaFuncAttributeMaxDynamicSharedMemorySize, SCAN_SMEM);

    wpack_kernel<<<64, 256>>>(Wih);
    xw_kernel<<<2048, 256, XW_SMEM>>>(x, bih, bhh);
    scan_kernel<<<128, 512, SCAN_SMEM>>>(Whh);
    fc_kernel<<<256, 256>>>(fcw, fcb, out);
}

// round 6
// speedup vs baseline: 1.7654x; 1.2054x over previous
#include <cuda_runtime.h>
#include <cstdint>
#include <math.h>

#define B_ 256
#define T_ 512
#define I_ 128
#define H_ 256

typedef unsigned long long ull;

// Scratch (static device globals — no dynamic allocation allowed).
__device__ float g_xw[(size_t)B_ * T_ * H_];   // [B][T][H] input projection + bias
__device__ float g_h[B_ * H_];                 // final hidden state
__device__ ull   g_wpack[I_ * (H_ / 2)];       // W_ih packed: [k][j2] = {W[2j2][k], W[2j2+1][k]}

// ---------------------------------------------------------------------------
// helpers
// ---------------------------------------------------------------------------
__device__ __forceinline__ void fma2(ull& acc, ull a, ull b) {
    asm("fma.rn.f32x2 %0, %1, %2, %0;" : "+l"(acc) : "l"(a), "l"(b));
}

__device__ __forceinline__ float unpack_sum(ull v) {
    float lo, hi;
    asm("mov.b64 {%0,%1}, %2;" : "=f"(lo), "=f"(hi) : "l"(v));
    return lo + hi;
}

__device__ __forceinline__ float2 unpack2(ull v) {
    float2 r;
    asm("mov.b64 {%0,%1}, %2;" : "=f"(r.x), "=f"(r.y) : "l"(v));
    return r;
}

__device__ __forceinline__ ull pack2(float a, float b) {
    ull u;
    asm("mov.b64 %0,{%1,%2};" : "=l"(u) : "f"(a), "f"(b));
    return u;
}

__device__ __forceinline__ ull dup1(float a) {
    ull u;
    asm("mov.b64 %0,{%1,%1};" : "=l"(u) : "f"(a));
    return u;
}

// ---------------------------------------------------------------------------
// Phase 0: pack W_ih k-major with j-pairs
// ---------------------------------------------------------------------------
__global__ void __launch_bounds__(256)
wpack_kernel(const float* __restrict__ Wih) {
    int t = blockIdx.x * 256 + threadIdx.x;   // 16384 total
    int j2 = t & 127, k = t >> 7;
    float a = __ldg(Wih + (2 * j2) * I_ + k);
    float b = __ldg(Wih + (2 * j2 + 1) * I_ + k);
    g_wpack[k * 128 + j2] = pack2(a, b);
}

// ---------------------------------------------------------------------------
// Phase 1: register-tiled f32x2 GEMM (unchanged from R4 — FMA-bound now)
// ---------------------------------------------------------------------------
__global__ void __launch_bounds__(256, 1)
xw_kernel(const float* __restrict__ x,
          const float* __restrict__ bih, const float* __restrict__ bhh) {
    extern __shared__ unsigned char smem_raw[];
    ull* xs = (ull*)smem_raw;                       // [r][k] dup, 128KB
    ull* ws = (ull*)(smem_raw + 128 * 128 * 8);     // [k][j2l], 64KB

    const int tid = threadIdx.x;
    const int jt  = blockIdx.x & 1;
    const int rt  = blockIdx.x >> 1;
    const int tx  = tid & 15;
    const int ty  = tid >> 4;

    {
        const float4* xg = (const float4*)(x + (size_t)rt * 128 * I_);
        for (int i = 0; i < 16; ++i) {
            int lin = tid + i * 256;
            float4 v = __ldg(xg + lin);
            int r = lin >> 5, kc = lin & 31;
            ulonglong2* d = (ulonglong2*)(xs + r * 128 + kc * 4);
            ulonglong2 u0; u0.x = dup1(v.x); u0.y = dup1(v.y);
            ulonglong2 u1; u1.x = dup1(v.z); u1.y = dup1(v.w);
            d[0] = u0; d[1] = u1;
        }
    }
    {
        const ulonglong2* wg = (const ulonglong2*)g_wpack;
        ulonglong2* wd = (ulonglong2*)ws;
        for (int i = 0; i < 16; ++i) {
            int lin = tid + i * 256;
            int k = lin >> 5, c = lin & 31;
            wd[k * 32 + c] = __ldg(wg + k * 64 + jt * 32 + c);
        }
    }
    __syncthreads();

    ull acc[8][4];
#pragma unroll
    for (int r = 0; r < 8; ++r)
#pragma unroll
        for (int j = 0; j < 4; ++j) acc[r][j] = 0ull;

    const ull* xrow = xs + (ty * 8) * 128;
    const ull* wcol = ws + tx;

#pragma unroll 4
    for (int k = 0; k < 128; ++k) {
        ull wv[4];
#pragma unroll
        for (int jj = 0; jj < 4; ++jj) wv[jj] = wcol[k * 64 + jj * 16];
#pragma unroll
        for (int r = 0; r < 8; ++r) {
            ull xv = xrow[r * 128 + k];
#pragma unroll
            for (int jj = 0; jj < 4; ++jj) fma2(acc[r][jj], xv, wv[jj]);
        }
    }

    float2 bb[4];
#pragma unroll
    for (int jj = 0; jj < 4; ++jj) {
        int j2 = jt * 64 + tx + 16 * jj;
        float2 b1 = __ldg(((const float2*)bih) + j2);
        float2 b2 = __ldg(((const float2*)bhh) + j2);
        bb[jj].x = b1.x + b2.x; bb[jj].y = b1.y + b2.y;
    }
    float2* outg = (float2*)g_xw;
#pragma unroll
    for (int r = 0; r < 8; ++r) {
        size_t row = (size_t)rt * 128 + ty * 8 + r;
#pragma unroll
        for (int jj = 0; jj < 4; ++jj) {
            float2 v = unpack2(acc[r][jj]);
            v.x += bb[jj].x; v.y += bb[jj].y;
            outg[row * 128 + jt * 64 + tx + 16 * jj] = v;
        }
    }
}

// ---------------------------------------------------------------------------
// Phase 2: recurrent scan — 128 CTAs x 256 threads, 2 batch rows per CTA.
// Thread (jq = tid&63, kq = tid>>6) owns j = 4jq..4jq+3 and k-quarter
// [64kq, 64kq+64). W_hh slice: 20 k2/j in regs (160 regs, no spill at 256
// thr), 12 k2/j via per-lane LDS.128 from smem (96KB). h broadcasts feed 16
// FFMA2 each. 4-way k reduction via psum; kq in {0,1} finalizes row kq.
// ---------------------------------------------------------------------------
#define NRK2 20   // k2 per j in registers
#define NSU2 6    // ull2 per j in smem (12 k2)

__global__ void __launch_bounds__(256, 1)
scan_kernel(const float* __restrict__ Whh) {
    extern __shared__ unsigned char smem_raw[];
    ulonglong2* Wsm2 = (ulonglong2*)smem_raw;                 // [24][256] = 96KB
    float* hbuf = (float*)(smem_raw + 4 * NSU2 * 256 * 16);   // [2][2][256] = 4KB
    ulonglong2* psum2 = (ulonglong2*)(hbuf + 1024);           // [2][3][2][64] = 12KB

    const int tid = threadIdx.x;
    const int jq  = tid & 63;
    const int kq  = tid >> 6;            // 0..3
    const int j0  = jq * 4;
    const int b0  = blockIdx.x * 2;

    // W registers: k2 idx [kq*32, kq*32+20) for each of 4 j's
    ull w[4][NRK2];
#pragma unroll
    for (int jj = 0; jj < 4; ++jj) {
        const ull* Wr = (const ull*)(Whh + (size_t)(j0 + jj) * H_) + kq * 32;
#pragma unroll
        for (int i = 0; i < NRK2; ++i) w[jj][i] = __ldg(Wr + i);
    }
    // W smem: ull2 idx [kq*16+10, kq*16+16) per j -> Wsm2[(jj*6+p)*256 + tid]
#pragma unroll
    for (int jj = 0; jj < 4; ++jj) {
        const ulonglong2* Wr2 = (const ulonglong2*)(Whh + (size_t)(j0 + jj) * H_);
#pragma unroll
        for (int p = 0; p < NSU2; ++p)
            Wsm2[(jj * NSU2 + p) * 256 + tid] = __ldg(Wr2 + kq * 16 + 10 + p);
    }

    // h0 = 0 (both parities)
    for (int i = tid; i < 1024; i += 256) hbuf[i] = 0.0f;
    __syncthreads();

    const ulonglong2* hb  = (const ulonglong2*)hbuf;   // [(p*2+row)*64 + k4]
    const ulonglong2* wsp = Wsm2 + tid;

    // xw stream: finalizer (kq<2) covers row b0+kq, cols j0..j0+3
    const float4* xwp = ((const float4*)g_xw) + ((size_t)(b0 + kq) * T_) * 64 + jq;
    float4 cur = make_float4(0.f, 0.f, 0.f, 0.f);
    if (kq < 2) cur = __ldg(xwp);

    for (int t = 0; t < T_; ++t) {
        const int p = t & 1;
        const ulonglong2* h0p = hb + (p * 2 + 0) * 64 + kq * 16;
        const ulonglong2* h1p = hb + (p * 2 + 1) * 64 + kq * 16;

        ull a[4][2];
#pragma unroll
        for (int jj = 0; jj < 4; ++jj) { a[jj][0] = 0ull; a[jj][1] = 0ull; }

        // register-W part: h ull2 idx 0..9
#pragma unroll
        for (int i2 = 0; i2 < NRK2 / 2; ++i2) {
            ulonglong2 h0 = h0p[i2], h1 = h1p[i2];
#pragma unroll
            for (int jj = 0; jj < 4; ++jj) {
                fma2(a[jj][0], w[jj][2 * i2], h0.x); fma2(a[jj][0], w[jj][2 * i2 + 1], h0.y);
                fma2(a[jj][1], w[jj][2 * i2], h1.x); fma2(a[jj][1], w[jj][2 * i2 + 1], h1.y);
            }
        }
        // smem-W part: h ull2 idx 10..15
#pragma unroll
        for (int pp = 0; pp < NSU2; ++pp) {
            ulonglong2 h0 = h0p[NRK2 / 2 + pp], h1 = h1p[NRK2 / 2 + pp];
#pragma unroll
            for (int jj = 0; jj < 4; ++jj) {
                ulonglong2 wv = wsp[(jj * NSU2 + pp) * 256];
                fma2(a[jj][0], wv.x, h0.x); fma2(a[jj][0], wv.y, h0.y);
                fma2(a[jj][1], wv.x, h1.x); fma2(a[jj][1], wv.y, h1.y);
            }
        }

        // prefetch next xw
        float4 nxt = make_float4(0.f, 0.f, 0.f, 0.f);
        if (kq < 2 && t + 1 < T_) nxt = __ldg(xwp + (size_t)(t + 1) * 64);

        // publish partials for rows I don't finalize.
        // row 0 finalized by kq=0 (contrib kq=1->s0, 2->s1, 3->s2)
        // row 1 finalized by kq=1 (contrib kq=0->s0, 2->s1, 3->s2)
        {
            if (kq == 0) {
                ulonglong2 u0; u0.x = a[0][1]; u0.y = a[1][1];
                ulonglong2 u1; u1.x = a[2][1]; u1.y = a[3][1];
                psum2[((1 * 3 + 0) * 2 + 0) * 64 + jq] = u0;
                psum2[((1 * 3 + 0) * 2 + 1) * 64 + jq] = u1;
            } else if (kq == 1) {
                ulonglong2 u0; u0.x = a[0][0]; u0.y = a[1][0];
                ulonglong2 u1; u1.x = a[2][0]; u1.y = a[3][0];
                psum2[((0 * 3 + 0) * 2 + 0) * 64 + jq] = u0;
                psum2[((0 * 3 + 0) * 2 + 1) * 64 + jq] = u1;
            } else {
                int s = kq - 1;  // 1 or 2
#pragma unroll
                for (int r = 0; r < 2; ++r) {
                    ulonglong2 u0; u0.x = a[0][r]; u0.y = a[1][r];
                    ulonglong2 u1; u1.x = a[2][r]; u1.y = a[3][r];
                    psum2[((r * 3 + s) * 2 + 0) * 64 + jq] = u0;
                    psum2[((r * 3 + s) * 2 + 1) * 64 + jq] = u1;
                }
            }
        }
        __syncthreads();

        if (kq < 2) {
            float s0 = unpack_sum(a[0][kq]) + cur.x;
            float s1 = unpack_sum(a[1][kq]) + cur.y;
            float s2 = unpack_sum(a[2][kq]) + cur.z;
            float s3 = unpack_sum(a[3][kq]) + cur.w;
#pragma unroll
            for (int s = 0; s < 3; ++s) {
                ulonglong2 u0 = psum2[((kq * 3 + s) * 2 + 0) * 64 + jq];
                ulonglong2 u1 = psum2[((kq * 3 + s) * 2 + 1) * 64 + jq];
                s0 += unpack_sum(u0.x); s1 += unpack_sum(u0.y);
                s2 += unpack_sum(u1.x); s3 += unpack_sum(u1.y);
            }
            float4 hv;
            hv.x = tanhf(s0); hv.y = tanhf(s1); hv.z = tanhf(s2); hv.w = tanhf(s3);
            ((float4*)hbuf)[(((p ^ 1) * 2) + kq) * 64 + jq] = hv;
            if (t == T_ - 1) ((float4*)g_h)[(b0 + kq) * 64 + jq] = hv;
            cur = nxt;
        }
        __syncthreads();
    }
}

// ---------------------------------------------------------------------------
// Phase 3: out[b] = g_h[b,:] . fc_w + fc_b
// ---------------------------------------------------------------------------
__global__ void __launch_bounds__(256)
fc_kernel(const float* __restrict__ fcw, const float* __restrict__ fcb,
          float* __restrict__ out) {
    const int b = blockIdx.x, tid = threadIdx.x;
    float v = g_h[b * H_ + tid] * __ldg(fcw + tid);
#pragma unroll
    for (int o = 16; o; o >>= 1) v += __shfl_down_sync(0xffffffffu, v, o);
    __shared__ float red[8];
    if ((tid & 31) == 0) red[tid >> 5] = v;
    __syncthreads();
    if (tid == 0) {
        float s = 0.f;
#pragma unroll
        for (int i = 0; i < 8; ++i) s += red[i];
        out[b] = s + __ldg(fcb);
    }
}

// ---------------------------------------------------------------------------
extern "C" void kernel_launch(void* const* d_in, const int* in_sizes, int n_in,
                              void* d_out, int out_size) {
    (void)in_sizes; (void)n_in; (void)out_size;
    const float* x   = (const float*)d_in[0];
    const float* Wih = (const float*)d_in[1];
    const float* Whh = (const float*)d_in[2];
    const float* bih = (const float*)d_in[3];
    const float* bhh = (const float*)d_in[4];
    const float* fcw = (const float*)d_in[5];
    const float* fcb = (const float*)d_in[6];
    float* out = (float*)d_out;

    const int XW_SMEM   = 128 * 128 * 8 + 128 * 64 * 8;                    // 192KB
    const int SCAN_SMEM = 4 * NSU2 * 256 * 16 + 1024 * 4 + 2 * 3 * 2 * 64 * 16;  // 112KB

    cudaFuncSetAttribute(xw_kernel, cudaFuncAttributeMaxDynamicSharedMemorySize, XW_SMEM);
    cudaFuncSetAttribute(scan_kernel, cudaFuncAttributeMaxDynamicSharedMemorySize, SCAN_SMEM);

    wpack_kernel<<<64, 256>>>(Wih);
    xw_kernel<<<2048, 256, XW_SMEM>>>(x, bih, bhh);
    scan_kernel<<<128, 256, SCAN_SMEM>>>(Whh);
    fc_kernel<<<256, 256>>>(fcw, fcb, out);
}